// round 11
// baseline (speedup 1.0000x reference)
#include <cuda_runtime.h>
#include <cuda_fp16.h>
#include <math.h>
#include <stdint.h>

// Problem constants
#define NROW 4096
#define BHALF 2048
#define DK   384
#define DMOD 128
#define NC   512

#define PROTO_CTAS 256

// Scratch (device globals)
// Single feature array scaled by sqrt(w_m): sims = g_F@g_F^T, proto = g_F@g_Cp^T
__device__ __half g_F[NROW * DK];
__device__ __half g_Cp[NC * DK];     // centroids * sqrt(w_m)/(conc+1e-12)
__device__ float g_rowsum[NROW];
__device__ float g_pos[NROW];
__device__ float g_sumexp[NROW];     // proto row sum of exp(logit)
__device__ float g_labval[NROW];     // proto logit at the label column
__device__ int   g_done;             // proto CTA completion counter

// ---------------------------------------------------------------------------
// helpers
// ---------------------------------------------------------------------------
__device__ __forceinline__ uint32_t smem_u32(const void* p) {
    uint32_t a;
    asm("{ .reg .u64 t; cvta.to.shared.u64 t, %1; cvt.u32.u64 %0, t; }" : "=r"(a) : "l"(p));
    return a;
}

// fast exp2 on FMA pipe
__device__ __forceinline__ float fexp2(float t) {
    float r = t + 12582912.0f;
    int   i = __float_as_int(r) - 0x4B400000;
    float f = t - (r - 12582912.0f);
    float p = 1.3333558e-3f;
    p = fmaf(p, f, 9.6181291e-3f);
    p = fmaf(p, f, 5.5504109e-2f);
    p = fmaf(p, f, 2.4022651e-1f);
    p = fmaf(p, f, 6.9314718e-1f);
    p = fmaf(p, f, 1.0f);
    return __int_as_float(__float_as_int(p) + (i << 23));
}

// f32-accumulate fp16 MMA (proto)
__device__ __forceinline__ void mma16816f(float* c, const uint32_t* a, const uint32_t* b) {
    asm volatile(
        "mma.sync.aligned.m16n8k16.row.col.f32.f16.f16.f32 "
        "{%0,%1,%2,%3},{%4,%5,%6,%7},{%8,%9},{%0,%1,%2,%3};"
        : "+f"(c[0]), "+f"(c[1]), "+f"(c[2]), "+f"(c[3])
        : "r"(a[0]), "r"(a[1]), "r"(a[2]), "r"(a[3]), "r"(b[0]), "r"(b[1]));
}
// f16-accumulate fp16 MMA (sims)
__device__ __forceinline__ void mma16816h(uint32_t* c, const uint32_t* a, const uint32_t* b) {
    asm volatile(
        "mma.sync.aligned.m16n8k16.row.col.f16.f16.f16.f16 "
        "{%0,%1},{%2,%3,%4,%5},{%6,%7},{%0,%1};"
        : "+r"(c[0]), "+r"(c[1])
        : "r"(a[0]), "r"(a[1]), "r"(a[2]), "r"(a[3]), "r"(b[0]), "r"(b[1]));
}

#define LDSM_X4(r0, r1, r2, r3, addr) \
    asm volatile("ldmatrix.sync.aligned.m8n8.x4.shared.b16 {%0,%1,%2,%3}, [%4];" \
                 : "=r"(r0), "=r"(r1), "=r"(r2), "=r"(r3) : "r"(addr))

// Packed tile layout: rows x 32 fp16 (64B/row), two rows per 128B line,
// XOR swizzle -> conflict-free for cp.async fill and ldmatrix.
__device__ __forceinline__ uint32_t sw_off(int r, int kb) {
    uint32_t L = ((uint32_t)(r >> 1) << 7) | ((uint32_t)(r & 1) << 6) | (uint32_t)kb;
    return L ^ ((L >> 3) & 0x70);
}

#define KTILES 12          // 384 / 32
#define CPA(dst, src) \
    asm volatile("cp.async.cg.shared.global [%0], [%1], 16;" :: "r"(dst), "l"(src))

// ---------------------------------------------------------------------------
// 0) prologue: normalize features (blocks < 768, 2 rows per warp for MLP=2)
//    + centroid scale / zero. sqrt(w_m) folded into features AND centroids.
// ---------------------------------------------------------------------------
__global__ void prep_kernel(const float* __restrict__ st_i,
                            const float* __restrict__ st_j,
                            const float* __restrict__ car_i,
                            const float* __restrict__ car_j,
                            const float* __restrict__ pl_i,
                            const float* __restrict__ pl_j,
                            const float* __restrict__ cst,
                            const float* __restrict__ ccar,
                            const float* __restrict__ cpl,
                            const float* __restrict__ conc,
                            float* __restrict__ out, int out_size) {
    int b = blockIdx.x;
    if (b < 768) {
        int wq = b * 8 + (threadIdx.x >> 5);   // 0..6143, handles rows 2wq, 2wq+1
        int lane = threadIdx.x & 31;
        int g0 = wq * 2;
        int t = g0 / BHALF;                    // rows g0, g0+1 same tensor (2048 even)
        int r0 = g0 % BHALF;
        const float* src;
        switch (t) {
            case 0: src = st_i;  break;
            case 1: src = st_j;  break;
            case 2: src = car_i; break;
            case 3: src = car_j; break;
            case 4: src = pl_i;  break;
            default: src = pl_j; break;
        }
        int m    = t >> 1;
        int half = t & 1;
        float sw = (m == 0) ? 0.6324555320336759f : 0.5477225575051661f;  // sqrt(w)

        float4 va = *reinterpret_cast<const float4*>(&src[(size_t)r0 * DMOD + lane * 4]);
        float4 vb = *reinterpret_cast<const float4*>(&src[(size_t)(r0 + 1) * DMOD + lane * 4]);
        float sa = va.x * va.x + va.y * va.y + va.z * va.z + va.w * va.w;
        float sb = vb.x * vb.x + vb.y * vb.y + vb.z * vb.z + vb.w * vb.w;
        #pragma unroll
        for (int o = 16; o; o >>= 1) {
            sa += __shfl_xor_sync(0xffffffffu, sa, o);
            sb += __shfl_xor_sync(0xffffffffu, sb, o);
        }
        float wsa = sw / fmaxf(sqrtf(sa), 1e-12f);
        float wsb = sw / fmaxf(sqrtf(sb), 1e-12f);

        size_t basea = (size_t)(half * BHALF + r0) * DK + m * DMOD + lane * 4;
        *reinterpret_cast<__half2*>(&g_F[basea])          = __floats2half2_rn(va.x * wsa, va.y * wsa);
        *reinterpret_cast<__half2*>(&g_F[basea + 2])      = __floats2half2_rn(va.z * wsa, va.w * wsa);
        *reinterpret_cast<__half2*>(&g_F[basea + DK])     = __floats2half2_rn(vb.x * wsb, vb.y * wsb);
        *reinterpret_cast<__half2*>(&g_F[basea + DK + 2]) = __floats2half2_rn(vb.z * wsb, vb.w * wsb);
    } else {
        int idx = (b - 768) * 256 + threadIdx.x;
        if (idx == 0) g_done = 0;
        if (idx < NROW) { g_rowsum[idx] = 0.0f; g_sumexp[idx] = 0.0f; }
        if (idx < out_size) out[idx] = 0.0f;
        if (idx < NC * DK) {
            int c   = idx / DK;
            int rem = idx % DK;
            int m   = rem >> 7;
            int d   = rem & 127;
            const float* cen = (m == 0) ? cst : ((m == 1) ? ccar : cpl);
            float sw = (m == 0) ? 0.6324555320336759f : 0.5477225575051661f;
            g_Cp[idx] = __float2half_rn(cen[c * DMOD + d] * (sw / (conc[m * NC + c] + 1e-12f)));
        }
    }
}

// ---------------------------------------------------------------------------
// 1) sims GEMM: S = g_F @ g_F^T, 128x128 tiles, triangular grid (528 CTAs),
//    fp16 inputs, fp16 accumulators, 3-stage cp.async, 1 barrier/iter.
// ---------------------------------------------------------------------------
__global__ void __launch_bounds__(256, 3) sims_f16() {
    __shared__ __align__(128) __half As[3][4096];   // 8 KB/stage
    __shared__ __align__(128) __half Bs[3][4096];

    // triangular decode: (by, bx) with bx >= by
    int n = blockIdx.x;
    int by = 0;
    while (n >= 32 - by) { n -= 32 - by; by++; }
    int bx = by + n;
    const bool diffblk = (bx != by);
    const int row0 = by * 128, col0 = bx * 128;

    const int tid  = threadIdx.x;
    const int lane = tid & 31;
    const int w    = tid >> 5;
    const int wm   = w >> 2;
    const int wn   = w & 3;
    const int g    = lane >> 2;
    const int t    = lane & 3;
    const int sub  = lane >> 3;
    const int lr   = lane & 7;

    uint32_t sA = smem_u32(As), sB = smem_u32(Bs);

    uint32_t dst_off[2];
    int src_off[2];
    #pragma unroll
    for (int l = 0; l < 2; l++) {
        int v = tid + l * 256;
        int r = v >> 2, c8 = v & 3;
        dst_off[l] = sw_off(r, c8 * 16);
        src_off[l] = r * DK + c8 * 8;
    }
    uint32_t offA[2][4], offB[2][2];
    #pragma unroll
    for (int s = 0; s < 2; s++) {
        int kbA = s * 32 + (sub >> 1) * 16;
        #pragma unroll
        for (int i = 0; i < 4; i++)
            offA[s][i] = sw_off(wm * 64 + i * 16 + (sub & 1) * 8 + lr, kbA);
        int kbB = s * 32 + (sub & 1) * 16;
        #pragma unroll
        for (int jp = 0; jp < 2; jp++)
            offB[s][jp] = sw_off(wn * 32 + jp * 16 + (sub >> 1) * 8 + lr, kbB);
    }

    uint32_t acc[4][4][2];
    #pragma unroll
    for (int i = 0; i < 4; i++)
        #pragma unroll
        for (int j = 0; j < 4; j++) { acc[i][j][0] = 0u; acc[i][j][1] = 0u; }

    const __half* Abase = g_F + (size_t)row0 * DK;
    const __half* Bbase = g_F + (size_t)col0 * DK;

    #pragma unroll
    for (int pf = 0; pf < 2; pf++) {
        #pragma unroll
        for (int l = 0; l < 2; l++) {
            CPA(sA + pf * 8192 + dst_off[l], __cvta_generic_to_global(Abase + pf * 32 + src_off[l]));
            CPA(sB + pf * 8192 + dst_off[l], __cvta_generic_to_global(Bbase + pf * 32 + src_off[l]));
        }
        asm volatile("cp.async.commit_group;" ::: "memory");
    }
    #pragma unroll 1
    for (int it = 0; it < KTILES; it++) {
        if (it < KTILES - 1) asm volatile("cp.async.wait_group 1;" ::: "memory");
        else                 asm volatile("cp.async.wait_group 0;" ::: "memory");
        __syncthreads();
        if (it + 2 < KTILES) {
            int st = (it + 2) % 3;
            #pragma unroll
            for (int l = 0; l < 2; l++) {
                CPA(sA + st * 8192 + dst_off[l], __cvta_generic_to_global(Abase + (it + 2) * 32 + src_off[l]));
                CPA(sB + st * 8192 + dst_off[l], __cvta_generic_to_global(Bbase + (it + 2) * 32 + src_off[l]));
            }
            asm volatile("cp.async.commit_group;" ::: "memory");
        }
        uint32_t bA = sA + (it % 3) * 8192, bB = sB + (it % 3) * 8192;
        #pragma unroll
        for (int s = 0; s < 2; s++) {
            uint32_t a[4][4], b[4][2];
            #pragma unroll
            for (int i = 0; i < 4; i++)
                LDSM_X4(a[i][0], a[i][1], a[i][2], a[i][3], bA + offA[s][i]);
            #pragma unroll
            for (int jp = 0; jp < 2; jp++)
                LDSM_X4(b[2 * jp][0], b[2 * jp][1], b[2 * jp + 1][0], b[2 * jp + 1][1],
                        bB + offB[s][jp]);
            #pragma unroll
            for (int i = 0; i < 4; i++)
                #pragma unroll
                for (int j = 0; j < 4; j++)
                    mma16816h(acc[i][j], a[i], b[j]);
        }
    }
    __syncthreads();

    // ---- epilogue (rs/rc reuse stage-0 smem) ----
    float* rs = reinterpret_cast<float*>(As);
    float* rc = rs + 128;
    if (tid < 128) { rs[tid] = 0.0f; rc[tid] = 0.0f; }
    __syncthreads();

    const float S2 = 2.8853900817779268f;   // 2/ln2 (1/TEMP = 2)
    float colsum[4][2];
    #pragma unroll
    for (int j = 0; j < 4; j++) { colsum[j][0] = 0.0f; colsum[j][1] = 0.0f; }

    #pragma unroll
    for (int i = 0; i < 4; i++) {
        #pragma unroll
        for (int h = 0; h < 2; h++) {
            int rl = wm * 64 + i * 16 + h * 8 + g;
            int gi = row0 + rl;
            int pj = (gi + BHALF) & (NROW - 1);
            float sum = 0.0f;
            #pragma unroll
            for (int j = 0; j < 4; j++) {
                float2 sv = __half22float2(*reinterpret_cast<__half2*>(&acc[i][j][h]));
                float e0 = fexp2(sv.x * S2);
                float e1 = fexp2(sv.y * S2);
                sum += e0 + e1;
                colsum[j][0] += e0;
                colsum[j][1] += e1;
                int gj = col0 + wn * 32 + j * 8 + 2 * t;
                if (gj == pj)     { g_pos[gi] = e0; if (diffblk) g_pos[gj]     = e0; }
                if (gj + 1 == pj) { g_pos[gi] = e1; if (diffblk) g_pos[gj + 1] = e1; }
            }
            sum += __shfl_xor_sync(0xffffffffu, sum, 1);
            sum += __shfl_xor_sync(0xffffffffu, sum, 2);
            if (t == 0) atomicAdd(&rs[rl], sum);
        }
    }
    if (diffblk) {
        #pragma unroll
        for (int j = 0; j < 4; j++) {
            #pragma unroll
            for (int p = 0; p < 2; p++) {
                float v = colsum[j][p];
                v += __shfl_xor_sync(0xffffffffu, v, 4);
                v += __shfl_xor_sync(0xffffffffu, v, 8);
                v += __shfl_xor_sync(0xffffffffu, v, 16);
                if (g == 0) atomicAdd(&rc[wn * 32 + j * 8 + 2 * t + p], v);
            }
        }
    }
    __syncthreads();
    if (tid < 128) {
        atomicAdd(&g_rowsum[row0 + tid], rs[tid]);
        if (diffblk) atomicAdd(&g_rowsum[col0 + tid], rc[tid]);
    }
}

// ---------------------------------------------------------------------------
// 2) proto GEMM + fused softmax + last-CTA finalize (fast __logf, no libm).
//    logits = g_F @ g_Cp^T (4096x512, K=384), 64x128 tiles -> 256 CTAs.
//    Runs after sims (stream order) so g_rowsum/g_pos are complete.
// ---------------------------------------------------------------------------
__global__ void __launch_bounds__(256, 3) proto_f16(const int* __restrict__ labels,
                                                    float* __restrict__ out) {
    __shared__ __align__(128) __half As[3][2048];   // 4 KB/stage
    __shared__ __align__(128) __half Bs[3][4096];   // 8 KB/stage
    __shared__ int s_flag;
    __shared__ float s_red[8];

    const int row0 = blockIdx.y * 64;
    const int col0 = blockIdx.x * 128;
    const int tid  = threadIdx.x;
    const int lane = tid & 31;
    const int w    = tid >> 5;
    const int wm   = w >> 2;
    const int wn   = w & 3;
    const int g    = lane >> 2;
    const int t    = lane & 3;
    const int sub  = lane >> 3;
    const int lr   = lane & 7;

    uint32_t sA = smem_u32(As), sB = smem_u32(Bs);

    uint32_t dstA;
    int srcA;
    {
        int r = tid >> 2, c8 = tid & 3;
        dstA = sw_off(r, c8 * 16);
        srcA = r * DK + c8 * 8;
    }
    uint32_t dstB[2];
    int srcB[2];
    #pragma unroll
    for (int l = 0; l < 2; l++) {
        int v = tid + l * 256;
        int r = v >> 2, c8 = v & 3;
        dstB[l] = sw_off(r, c8 * 16);
        srcB[l] = r * DK + c8 * 8;
    }
    uint32_t offA[2][2], offB[2][2];
    #pragma unroll
    for (int s = 0; s < 2; s++) {
        int kbA = s * 32 + (sub >> 1) * 16;
        #pragma unroll
        for (int i = 0; i < 2; i++)
            offA[s][i] = sw_off(wm * 32 + i * 16 + (sub & 1) * 8 + lr, kbA);
        int kbB = s * 32 + (sub & 1) * 16;
        #pragma unroll
        for (int jp = 0; jp < 2; jp++)
            offB[s][jp] = sw_off(wn * 32 + jp * 16 + (sub >> 1) * 8 + lr, kbB);
    }

    float acc[2][4][4];
    #pragma unroll
    for (int i = 0; i < 2; i++)
        #pragma unroll
        for (int j = 0; j < 4; j++)
            #pragma unroll
            for (int r = 0; r < 4; r++) acc[i][j][r] = 0.0f;

    const __half* Abase = g_F + (size_t)row0 * DK;
    const __half* Bbase = g_Cp + (size_t)col0 * DK;

    #pragma unroll
    for (int pf = 0; pf < 2; pf++) {
        CPA(sA + pf * 4096 + dstA, __cvta_generic_to_global(Abase + pf * 32 + srcA));
        #pragma unroll
        for (int l = 0; l < 2; l++)
            CPA(sB + pf * 8192 + dstB[l], __cvta_generic_to_global(Bbase + pf * 32 + srcB[l]));
        asm volatile("cp.async.commit_group;" ::: "memory");
    }
    #pragma unroll 1
    for (int it = 0; it < KTILES; it++) {
        if (it < KTILES - 1) asm volatile("cp.async.wait_group 1;" ::: "memory");
        else                 asm volatile("cp.async.wait_group 0;" ::: "memory");
        __syncthreads();
        if (it + 2 < KTILES) {
            int st = (it + 2) % 3;
            CPA(sA + st * 4096 + dstA, __cvta_generic_to_global(Abase + (it + 2) * 32 + srcA));
            #pragma unroll
            for (int l = 0; l < 2; l++)
                CPA(sB + st * 8192 + dstB[l], __cvta_generic_to_global(Bbase + (it + 2) * 32 + srcB[l]));
            asm volatile("cp.async.commit_group;" ::: "memory");
        }
        uint32_t bA = sA + (it % 3) * 4096, bB = sB + (it % 3) * 8192;
        #pragma unroll
        for (int s = 0; s < 2; s++) {
            uint32_t a[2][4], b[4][2];
            #pragma unroll
            for (int i = 0; i < 2; i++)
                LDSM_X4(a[i][0], a[i][1], a[i][2], a[i][3], bA + offA[s][i]);
            #pragma unroll
            for (int jp = 0; jp < 2; jp++)
                LDSM_X4(b[2 * jp][0], b[2 * jp][1], b[2 * jp + 1][0], b[2 * jp + 1][1],
                        bB + offB[s][jp]);
            #pragma unroll
            for (int i = 0; i < 2; i++)
                #pragma unroll
                for (int j = 0; j < 4; j++)
                    mma16816f(acc[i][j], a[i], b[j]);
        }
    }

    // ---- fused softmax epilogue ----
    const float LOG2E = 1.4426950408889634f;
    #pragma unroll
    for (int i = 0; i < 2; i++) {
        #pragma unroll
        for (int h = 0; h < 2; h++) {
            int gi  = row0 + wm * 32 + i * 16 + h * 8 + g;
            int lab = labels[gi];
            float sum = 0.0f;
            #pragma unroll
            for (int j = 0; j < 4; j++) {
                float l0 = acc[i][j][2 * h];
                float l1 = acc[i][j][2 * h + 1];
                sum += fexp2(l0 * LOG2E) + fexp2(l1 * LOG2E);
                int gj = col0 + wn * 32 + j * 8 + 2 * t;
                if (gj == lab)     g_labval[gi] = l0;
                if (gj + 1 == lab) g_labval[gi] = l1;
            }
            sum += __shfl_xor_sync(0xffffffffu, sum, 1);
            sum += __shfl_xor_sync(0xffffffffu, sum, 2);
            if (t == 0) atomicAdd(&g_sumexp[gi], sum);
        }
    }

    // ---- last-CTA finalize (release fence -> counter -> acquire fence) ----
    __syncthreads();
    if (tid == 0) {
        __threadfence();                           // release our stores/atomics
        int prev = atomicAdd(&g_done, 1);
        s_flag = (prev == PROTO_CTAS - 1) ? 1 : 0;
    }
    __syncthreads();
    if (s_flag) {
        __threadfence();                           // acquire others' stores
        float loss = 0.0f;
        #pragma unroll 4
        for (int row = tid; row < NROW; row += 256) {
            float loss2 = __logf(g_sumexp[row]) - g_labval[row];
            float loss1 = __logf((g_rowsum[row] - 7.3890560989306495f) / g_pos[row]); // diag=e^2
            loss += loss1 + loss2;
        }
        #pragma unroll
        for (int o = 16; o; o >>= 1) loss += __shfl_xor_sync(0xffffffffu, loss, o);
        if (lane == 0) s_red[w] = loss;
        __syncthreads();
        if (tid == 0) {
            float tot = 0.0f;
            #pragma unroll
            for (int i = 0; i < 8; i++) tot += s_red[i];
            out[0] = tot * (1.0f / NROW);
        }
    }
}

// ---------------------------------------------------------------------------
extern "C" void kernel_launch(void* const* d_in, const int* in_sizes, int n_in,
                              void* d_out, int out_size) {
    const float* st_i  = (const float*)d_in[0];
    const float* st_j  = (const float*)d_in[1];
    const float* car_i = (const float*)d_in[2];
    const float* car_j = (const float*)d_in[3];
    const float* pl_i  = (const float*)d_in[4];
    const float* pl_j  = (const float*)d_in[5];
    const int*   lab   = (const int*)d_in[6];
    const float* cst   = (const float*)d_in[7];
    const float* ccar  = (const float*)d_in[8];
    const float* cpl   = (const float*)d_in[9];
    const float* conc  = (const float*)d_in[10];
    float* out = (float*)d_out;

    prep_kernel<<<768 + 768, 256>>>(st_i, st_j, car_i, car_j, pl_i, pl_j,
                                    cst, ccar, cpl, conc, out, out_size);

    sims_f16<<<528, 256>>>();                  // triangular grid

    dim3 gp(NC / 128, NROW / 64);              // 4 x 64 = 256 CTAs
    proto_f16<<<gp, 256>>>(lab, out);
}

// round 12
// speedup vs baseline: 1.1517x; 1.1517x over previous
#include <cuda_runtime.h>
#include <cuda_fp16.h>
#include <math.h>
#include <stdint.h>

// Problem constants
#define NROW 4096
#define BHALF 2048
#define DK   384
#define DMOD 128
#define NC   512

// Scratch (device globals)
// Single feature array scaled by sqrt(w_m): sims = g_F@g_F^T, proto = g_F@g_Cp^T
__device__ __half g_F[NROW * DK];
__device__ __half g_Cp[NC * DK];     // centroids * sqrt(w_m)/(conc+1e-12)
__device__ float g_rowsum[NROW];
__device__ float g_pos[NROW];
__device__ float g_sumexp[NROW];     // proto row sum of exp(logit)
__device__ float g_labval[NROW];     // proto logit at the label column

// ---------------------------------------------------------------------------
// helpers
// ---------------------------------------------------------------------------
__device__ __forceinline__ uint32_t smem_u32(const void* p) {
    uint32_t a;
    asm("{ .reg .u64 t; cvta.to.shared.u64 t, %1; cvt.u32.u64 %0, t; }" : "=r"(a) : "l"(p));
    return a;
}

// fast exp2 on FMA pipe
__device__ __forceinline__ float fexp2(float t) {
    float r = t + 12582912.0f;
    int   i = __float_as_int(r) - 0x4B400000;
    float f = t - (r - 12582912.0f);
    float p = 1.3333558e-3f;
    p = fmaf(p, f, 9.6181291e-3f);
    p = fmaf(p, f, 5.5504109e-2f);
    p = fmaf(p, f, 2.4022651e-1f);
    p = fmaf(p, f, 6.9314718e-1f);
    p = fmaf(p, f, 1.0f);
    return __int_as_float(__float_as_int(p) + (i << 23));
}

// f32-accumulate fp16 MMA (proto)
__device__ __forceinline__ void mma16816f(float* c, const uint32_t* a, const uint32_t* b) {
    asm volatile(
        "mma.sync.aligned.m16n8k16.row.col.f32.f16.f16.f32 "
        "{%0,%1,%2,%3},{%4,%5,%6,%7},{%8,%9},{%0,%1,%2,%3};"
        : "+f"(c[0]), "+f"(c[1]), "+f"(c[2]), "+f"(c[3])
        : "r"(a[0]), "r"(a[1]), "r"(a[2]), "r"(a[3]), "r"(b[0]), "r"(b[1]));
}
// f16-accumulate fp16 MMA (sims)
__device__ __forceinline__ void mma16816h(uint32_t* c, const uint32_t* a, const uint32_t* b) {
    asm volatile(
        "mma.sync.aligned.m16n8k16.row.col.f16.f16.f16.f16 "
        "{%0,%1},{%2,%3,%4,%5},{%6,%7},{%0,%1};"
        : "+r"(c[0]), "+r"(c[1])
        : "r"(a[0]), "r"(a[1]), "r"(a[2]), "r"(a[3]), "r"(b[0]), "r"(b[1]));
}

#define LDSM_X4(r0, r1, r2, r3, addr) \
    asm volatile("ldmatrix.sync.aligned.m8n8.x4.shared.b16 {%0,%1,%2,%3}, [%4];" \
                 : "=r"(r0), "=r"(r1), "=r"(r2), "=r"(r3) : "r"(addr))

// Packed tile layout: rows x 32 fp16 (64B/row), two rows per 128B line,
// XOR swizzle -> conflict-free for cp.async fill and ldmatrix.
__device__ __forceinline__ uint32_t sw_off(int r, int kb) {
    uint32_t L = ((uint32_t)(r >> 1) << 7) | ((uint32_t)(r & 1) << 6) | (uint32_t)kb;
    return L ^ ((L >> 3) & 0x70);
}

#define KTILES 12          // 384 / 32
#define CPA(dst, src) \
    asm volatile("cp.async.cg.shared.global [%0], [%1], 16;" :: "r"(dst), "l"(src))

// ---------------------------------------------------------------------------
// 0) prologue: normalize features (blocks < 768, 2 rows per warp -> MLP=2)
//    + centroid scale / zero. sqrt(w_m) folded into features AND centroids.
// ---------------------------------------------------------------------------
__global__ void prep_kernel(const float* __restrict__ st_i,
                            const float* __restrict__ st_j,
                            const float* __restrict__ car_i,
                            const float* __restrict__ car_j,
                            const float* __restrict__ pl_i,
                            const float* __restrict__ pl_j,
                            const float* __restrict__ cst,
                            const float* __restrict__ ccar,
                            const float* __restrict__ cpl,
                            const float* __restrict__ conc,
                            float* __restrict__ out, int out_size) {
    int b = blockIdx.x;
    if (b < 768) {
        int wq = b * 8 + (threadIdx.x >> 5);   // warp handles rows 2wq, 2wq+1
        int lane = threadIdx.x & 31;
        int g0 = wq * 2;
        int t = g0 / BHALF;                    // both rows in same tensor (2048 even)
        int r0 = g0 % BHALF;
        const float* src;
        switch (t) {
            case 0: src = st_i;  break;
            case 1: src = st_j;  break;
            case 2: src = car_i; break;
            case 3: src = car_j; break;
            case 4: src = pl_i;  break;
            default: src = pl_j; break;
        }
        int m    = t >> 1;
        int half = t & 1;
        float sw = (m == 0) ? 0.6324555320336759f : 0.5477225575051661f;  // sqrt(w)

        float4 va = *reinterpret_cast<const float4*>(&src[(size_t)r0 * DMOD + lane * 4]);
        float4 vb = *reinterpret_cast<const float4*>(&src[(size_t)(r0 + 1) * DMOD + lane * 4]);
        float sa = va.x * va.x + va.y * va.y + va.z * va.z + va.w * va.w;
        float sb = vb.x * vb.x + vb.y * vb.y + vb.z * vb.z + vb.w * vb.w;
        #pragma unroll
        for (int o = 16; o; o >>= 1) {
            sa += __shfl_xor_sync(0xffffffffu, sa, o);
            sb += __shfl_xor_sync(0xffffffffu, sb, o);
        }
        float wsa = sw / fmaxf(sqrtf(sa), 1e-12f);
        float wsb = sw / fmaxf(sqrtf(sb), 1e-12f);

        size_t basea = (size_t)(half * BHALF + r0) * DK + m * DMOD + lane * 4;
        *reinterpret_cast<__half2*>(&g_F[basea])          = __floats2half2_rn(va.x * wsa, va.y * wsa);
        *reinterpret_cast<__half2*>(&g_F[basea + 2])      = __floats2half2_rn(va.z * wsa, va.w * wsa);
        *reinterpret_cast<__half2*>(&g_F[basea + DK])     = __floats2half2_rn(vb.x * wsb, vb.y * wsb);
        *reinterpret_cast<__half2*>(&g_F[basea + DK + 2]) = __floats2half2_rn(vb.z * wsb, vb.w * wsb);
    } else {
        int idx = (b - 768) * 256 + threadIdx.x;
        if (idx < NROW) { g_rowsum[idx] = 0.0f; g_sumexp[idx] = 0.0f; }
        if (idx < out_size) out[idx] = 0.0f;
        if (idx < NC * DK) {
            int c   = idx / DK;
            int rem = idx % DK;
            int m   = rem >> 7;
            int d   = rem & 127;
            const float* cen = (m == 0) ? cst : ((m == 1) ? ccar : cpl);
            float sw = (m == 0) ? 0.6324555320336759f : 0.5477225575051661f;
            g_Cp[idx] = __float2half_rn(cen[c * DMOD + d] * (sw / (conc[m * NC + c] + 1e-12f)));
        }
    }
}

// ---------------------------------------------------------------------------
// 1) sims GEMM: S = g_F @ g_F^T, 128x128 tiles, triangular grid (528 CTAs),
//    fp16 inputs, fp16 accumulators, 3-stage cp.async, 1 barrier/iter.
// ---------------------------------------------------------------------------
__global__ void __launch_bounds__(256, 3) sims_f16() {
    __shared__ __align__(128) __half As[3][4096];   // 8 KB/stage
    __shared__ __align__(128) __half Bs[3][4096];

    // triangular decode: (by, bx) with bx >= by
    int n = blockIdx.x;
    int by = 0;
    while (n >= 32 - by) { n -= 32 - by; by++; }
    int bx = by + n;
    const bool diffblk = (bx != by);
    const int row0 = by * 128, col0 = bx * 128;

    const int tid  = threadIdx.x;
    const int lane = tid & 31;
    const int w    = tid >> 5;
    const int wm   = w >> 2;
    const int wn   = w & 3;
    const int g    = lane >> 2;
    const int t    = lane & 3;
    const int sub  = lane >> 3;
    const int lr   = lane & 7;

    uint32_t sA = smem_u32(As), sB = smem_u32(Bs);

    uint32_t dst_off[2];
    int src_off[2];
    #pragma unroll
    for (int l = 0; l < 2; l++) {
        int v = tid + l * 256;
        int r = v >> 2, c8 = v & 3;
        dst_off[l] = sw_off(r, c8 * 16);
        src_off[l] = r * DK + c8 * 8;
    }
    uint32_t offA[2][4], offB[2][2];
    #pragma unroll
    for (int s = 0; s < 2; s++) {
        int kbA = s * 32 + (sub >> 1) * 16;
        #pragma unroll
        for (int i = 0; i < 4; i++)
            offA[s][i] = sw_off(wm * 64 + i * 16 + (sub & 1) * 8 + lr, kbA);
        int kbB = s * 32 + (sub & 1) * 16;
        #pragma unroll
        for (int jp = 0; jp < 2; jp++)
            offB[s][jp] = sw_off(wn * 32 + jp * 16 + (sub >> 1) * 8 + lr, kbB);
    }

    uint32_t acc[4][4][2];
    #pragma unroll
    for (int i = 0; i < 4; i++)
        #pragma unroll
        for (int j = 0; j < 4; j++) { acc[i][j][0] = 0u; acc[i][j][1] = 0u; }

    const __half* Abase = g_F + (size_t)row0 * DK;
    const __half* Bbase = g_F + (size_t)col0 * DK;

    #pragma unroll
    for (int pf = 0; pf < 2; pf++) {
        #pragma unroll
        for (int l = 0; l < 2; l++) {
            CPA(sA + pf * 8192 + dst_off[l], __cvta_generic_to_global(Abase + pf * 32 + src_off[l]));
            CPA(sB + pf * 8192 + dst_off[l], __cvta_generic_to_global(Bbase + pf * 32 + src_off[l]));
        }
        asm volatile("cp.async.commit_group;" ::: "memory");
    }
    #pragma unroll 1
    for (int it = 0; it < KTILES; it++) {
        if (it < KTILES - 1) asm volatile("cp.async.wait_group 1;" ::: "memory");
        else                 asm volatile("cp.async.wait_group 0;" ::: "memory");
        __syncthreads();
        if (it + 2 < KTILES) {
            int st = (it + 2) % 3;
            #pragma unroll
            for (int l = 0; l < 2; l++) {
                CPA(sA + st * 8192 + dst_off[l], __cvta_generic_to_global(Abase + (it + 2) * 32 + src_off[l]));
                CPA(sB + st * 8192 + dst_off[l], __cvta_generic_to_global(Bbase + (it + 2) * 32 + src_off[l]));
            }
            asm volatile("cp.async.commit_group;" ::: "memory");
        }
        uint32_t bA = sA + (it % 3) * 8192, bB = sB + (it % 3) * 8192;
        #pragma unroll
        for (int s = 0; s < 2; s++) {
            uint32_t a[4][4], b[4][2];
            #pragma unroll
            for (int i = 0; i < 4; i++)
                LDSM_X4(a[i][0], a[i][1], a[i][2], a[i][3], bA + offA[s][i]);
            #pragma unroll
            for (int jp = 0; jp < 2; jp++)
                LDSM_X4(b[2 * jp][0], b[2 * jp][1], b[2 * jp + 1][0], b[2 * jp + 1][1],
                        bB + offB[s][jp]);
            #pragma unroll
            for (int i = 0; i < 4; i++)
                #pragma unroll
                for (int j = 0; j < 4; j++)
                    mma16816h(acc[i][j], a[i], b[j]);
        }
    }
    __syncthreads();

    // ---- epilogue (rs/rc reuse stage-0 smem) ----
    float* rs = reinterpret_cast<float*>(As);
    float* rc = rs + 128;
    if (tid < 128) { rs[tid] = 0.0f; rc[tid] = 0.0f; }
    __syncthreads();

    const float S2 = 2.8853900817779268f;   // 2/ln2 (1/TEMP = 2)
    float colsum[4][2];
    #pragma unroll
    for (int j = 0; j < 4; j++) { colsum[j][0] = 0.0f; colsum[j][1] = 0.0f; }

    #pragma unroll
    for (int i = 0; i < 4; i++) {
        #pragma unroll
        for (int h = 0; h < 2; h++) {
            int rl = wm * 64 + i * 16 + h * 8 + g;
            int gi = row0 + rl;
            int pj = (gi + BHALF) & (NROW - 1);
            float sum = 0.0f;
            #pragma unroll
            for (int j = 0; j < 4; j++) {
                float2 sv = __half22float2(*reinterpret_cast<__half2*>(&acc[i][j][h]));
                float e0 = fexp2(sv.x * S2);
                float e1 = fexp2(sv.y * S2);
                sum += e0 + e1;
                colsum[j][0] += e0;
                colsum[j][1] += e1;
                int gj = col0 + wn * 32 + j * 8 + 2 * t;
                if (gj == pj)     { g_pos[gi] = e0; if (diffblk) g_pos[gj]     = e0; }
                if (gj + 1 == pj) { g_pos[gi] = e1; if (diffblk) g_pos[gj + 1] = e1; }
            }
            sum += __shfl_xor_sync(0xffffffffu, sum, 1);
            sum += __shfl_xor_sync(0xffffffffu, sum, 2);
            if (t == 0) atomicAdd(&rs[rl], sum);
        }
    }
    if (diffblk) {
        #pragma unroll
        for (int j = 0; j < 4; j++) {
            #pragma unroll
            for (int p = 0; p < 2; p++) {
                float v = colsum[j][p];
                v += __shfl_xor_sync(0xffffffffu, v, 4);
                v += __shfl_xor_sync(0xffffffffu, v, 8);
                v += __shfl_xor_sync(0xffffffffu, v, 16);
                if (g == 0) atomicAdd(&rc[wn * 32 + j * 8 + 2 * t + p], v);
            }
        }
    }
    __syncthreads();
    if (tid < 128) {
        atomicAdd(&g_rowsum[row0 + tid], rs[tid]);
        if (diffblk) atomicAdd(&g_rowsum[col0 + tid], rc[tid]);
    }
}

// ---------------------------------------------------------------------------
// 2) proto GEMM + fused softmax: logits = g_F @ g_Cp^T (4096x512, K=384).
//    64x128 tiles -> 256 CTAs. Bounded logits -> max-free distributive
//    sum-exp; per-row atomics; label logit stored directly.
// ---------------------------------------------------------------------------
__global__ void __launch_bounds__(256, 3) proto_f16(const int* __restrict__ labels) {
    __shared__ __align__(128) __half As[3][2048];   // 4 KB/stage
    __shared__ __align__(128) __half Bs[3][4096];   // 8 KB/stage

    const int row0 = blockIdx.y * 64;
    const int col0 = blockIdx.x * 128;
    const int tid  = threadIdx.x;
    const int lane = tid & 31;
    const int w    = tid >> 5;
    const int wm   = w >> 2;
    const int wn   = w & 3;
    const int g    = lane >> 2;
    const int t    = lane & 3;
    const int sub  = lane >> 3;
    const int lr   = lane & 7;

    uint32_t sA = smem_u32(As), sB = smem_u32(Bs);

    uint32_t dstA;
    int srcA;
    {
        int r = tid >> 2, c8 = tid & 3;
        dstA = sw_off(r, c8 * 16);
        srcA = r * DK + c8 * 8;
    }
    uint32_t dstB[2];
    int srcB[2];
    #pragma unroll
    for (int l = 0; l < 2; l++) {
        int v = tid + l * 256;
        int r = v >> 2, c8 = v & 3;
        dstB[l] = sw_off(r, c8 * 16);
        srcB[l] = r * DK + c8 * 8;
    }
    uint32_t offA[2][2], offB[2][2];
    #pragma unroll
    for (int s = 0; s < 2; s++) {
        int kbA = s * 32 + (sub >> 1) * 16;
        #pragma unroll
        for (int i = 0; i < 2; i++)
            offA[s][i] = sw_off(wm * 32 + i * 16 + (sub & 1) * 8 + lr, kbA);
        int kbB = s * 32 + (sub & 1) * 16;
        #pragma unroll
        for (int jp = 0; jp < 2; jp++)
            offB[s][jp] = sw_off(wn * 32 + jp * 16 + (sub >> 1) * 8 + lr, kbB);
    }

    float acc[2][4][4];
    #pragma unroll
    for (int i = 0; i < 2; i++)
        #pragma unroll
        for (int j = 0; j < 4; j++)
            #pragma unroll
            for (int r = 0; r < 4; r++) acc[i][j][r] = 0.0f;

    const __half* Abase = g_F + (size_t)row0 * DK;
    const __half* Bbase = g_Cp + (size_t)col0 * DK;

    #pragma unroll
    for (int pf = 0; pf < 2; pf++) {
        CPA(sA + pf * 4096 + dstA, __cvta_generic_to_global(Abase + pf * 32 + srcA));
        #pragma unroll
        for (int l = 0; l < 2; l++)
            CPA(sB + pf * 8192 + dstB[l], __cvta_generic_to_global(Bbase + pf * 32 + srcB[l]));
        asm volatile("cp.async.commit_group;" ::: "memory");
    }
    #pragma unroll 1
    for (int it = 0; it < KTILES; it++) {
        if (it < KTILES - 1) asm volatile("cp.async.wait_group 1;" ::: "memory");
        else                 asm volatile("cp.async.wait_group 0;" ::: "memory");
        __syncthreads();
        if (it + 2 < KTILES) {
            int st = (it + 2) % 3;
            CPA(sA + st * 4096 + dstA, __cvta_generic_to_global(Abase + (it + 2) * 32 + srcA));
            #pragma unroll
            for (int l = 0; l < 2; l++)
                CPA(sB + st * 8192 + dstB[l], __cvta_generic_to_global(Bbase + (it + 2) * 32 + srcB[l]));
            asm volatile("cp.async.commit_group;" ::: "memory");
        }
        uint32_t bA = sA + (it % 3) * 4096, bB = sB + (it % 3) * 8192;
        #pragma unroll
        for (int s = 0; s < 2; s++) {
            uint32_t a[2][4], b[4][2];
            #pragma unroll
            for (int i = 0; i < 2; i++)
                LDSM_X4(a[i][0], a[i][1], a[i][2], a[i][3], bA + offA[s][i]);
            #pragma unroll
            for (int jp = 0; jp < 2; jp++)
                LDSM_X4(b[2 * jp][0], b[2 * jp][1], b[2 * jp + 1][0], b[2 * jp + 1][1],
                        bB + offB[s][jp]);
            #pragma unroll
            for (int i = 0; i < 2; i++)
                #pragma unroll
                for (int j = 0; j < 4; j++)
                    mma16816f(acc[i][j], a[i], b[j]);
        }
    }

    // ---- fused softmax epilogue ----
    const float LOG2E = 1.4426950408889634f;
    #pragma unroll
    for (int i = 0; i < 2; i++) {
        #pragma unroll
        for (int h = 0; h < 2; h++) {
            int gi  = row0 + wm * 32 + i * 16 + h * 8 + g;
            int lab = labels[gi];
            float sum = 0.0f;
            #pragma unroll
            for (int j = 0; j < 4; j++) {
                float l0 = acc[i][j][2 * h];
                float l1 = acc[i][j][2 * h + 1];
                sum += fexp2(l0 * LOG2E) + fexp2(l1 * LOG2E);
                int gj = col0 + wn * 32 + j * 8 + 2 * t;
                if (gj == lab)     g_labval[gi] = l0;
                if (gj + 1 == lab) g_labval[gi] = l1;
            }
            sum += __shfl_xor_sync(0xffffffffu, sum, 1);
            sum += __shfl_xor_sync(0xffffffffu, sum, 2);
            if (t == 0) atomicAdd(&g_sumexp[gi], sum);
        }
    }
}

// ---------------------------------------------------------------------------
// 3) Finalize: trivial per-row combine -> mean (4096 threads)
// ---------------------------------------------------------------------------
__global__ void finalize_kernel(float* __restrict__ out) {
    int row  = blockIdx.x * blockDim.x + threadIdx.x;
    int lane = threadIdx.x & 31;
    float loss = 0.0f;
    if (row < NROW) {
        float loss2 = __logf(g_sumexp[row]) - g_labval[row];
        float loss1 = __logf((g_rowsum[row] - 7.3890560989306495f) / g_pos[row]); // diag=e^2
        loss = (loss1 + loss2) * (1.0f / NROW);
    }
    #pragma unroll
    for (int o = 16; o; o >>= 1) loss += __shfl_xor_sync(0xffffffffu, loss, o);
    if (lane == 0) atomicAdd(out, loss);
}

// ---------------------------------------------------------------------------
extern "C" void kernel_launch(void* const* d_in, const int* in_sizes, int n_in,
                              void* d_out, int out_size) {
    const float* st_i  = (const float*)d_in[0];
    const float* st_j  = (const float*)d_in[1];
    const float* car_i = (const float*)d_in[2];
    const float* car_j = (const float*)d_in[3];
    const float* pl_i  = (const float*)d_in[4];
    const float* pl_j  = (const float*)d_in[5];
    const int*   lab   = (const int*)d_in[6];
    const float* cst   = (const float*)d_in[7];
    const float* ccar  = (const float*)d_in[8];
    const float* cpl   = (const float*)d_in[9];
    const float* conc  = (const float*)d_in[10];
    float* out = (float*)d_out;

    prep_kernel<<<768 + 768, 256>>>(st_i, st_j, car_i, car_j, pl_i, pl_j,
                                    cst, ccar, cpl, conc, out, out_size);

    sims_f16<<<528, 256>>>();                  // triangular grid

    dim3 gp(NC / 128, NROW / 64);              // 4 x 64 = 256 CTAs
    proto_f16<<<gp, 256>>>(lab);

    finalize_kernel<<<NROW / 256, 256>>>(out);
}

// round 13
// speedup vs baseline: 1.2189x; 1.0584x over previous
#include <cuda_runtime.h>
#include <cuda_fp16.h>
#include <math.h>
#include <stdint.h>

// Problem constants
#define NROW 4096
#define BHALF 2048
#define DK   384
#define DMOD 128
#define NC   512

#define SIMS_CTAS 528
#define PROTO_CTAS 256

// Scratch (device globals)
// Single feature array scaled by sqrt(w_m): sims = g_F@g_F^T, proto = g_F@g_Cp^T
__device__ __half g_F[NROW * DK];
__device__ __half g_Cp[NC * DK];     // centroids * sqrt(w_m)/(conc+1e-12)
__device__ float g_rowsum[NROW];
__device__ float g_pos[NROW];
__device__ float g_sumexp[NROW];     // proto row sum of exp(logit)
__device__ float g_labval[NROW];     // proto logit at the label column

// ---------------------------------------------------------------------------
// helpers
// ---------------------------------------------------------------------------
__device__ __forceinline__ uint32_t smem_u32(const void* p) {
    uint32_t a;
    asm("{ .reg .u64 t; cvta.to.shared.u64 t, %1; cvt.u32.u64 %0, t; }" : "=r"(a) : "l"(p));
    return a;
}

// fast exp2 on FMA pipe
__device__ __forceinline__ float fexp2(float t) {
    float r = t + 12582912.0f;
    int   i = __float_as_int(r) - 0x4B400000;
    float f = t - (r - 12582912.0f);
    float p = 1.3333558e-3f;
    p = fmaf(p, f, 9.6181291e-3f);
    p = fmaf(p, f, 5.5504109e-2f);
    p = fmaf(p, f, 2.4022651e-1f);
    p = fmaf(p, f, 6.9314718e-1f);
    p = fmaf(p, f, 1.0f);
    return __int_as_float(__float_as_int(p) + (i << 23));
}

// f32-accumulate fp16 MMA (proto)
__device__ __forceinline__ void mma16816f(float* c, const uint32_t* a, const uint32_t* b) {
    asm volatile(
        "mma.sync.aligned.m16n8k16.row.col.f32.f16.f16.f32 "
        "{%0,%1,%2,%3},{%4,%5,%6,%7},{%8,%9},{%0,%1,%2,%3};"
        : "+f"(c[0]), "+f"(c[1]), "+f"(c[2]), "+f"(c[3])
        : "r"(a[0]), "r"(a[1]), "r"(a[2]), "r"(a[3]), "r"(b[0]), "r"(b[1]));
}
// f16-accumulate fp16 MMA (sims)
__device__ __forceinline__ void mma16816h(uint32_t* c, const uint32_t* a, const uint32_t* b) {
    asm volatile(
        "mma.sync.aligned.m16n8k16.row.col.f16.f16.f16.f16 "
        "{%0,%1},{%2,%3,%4,%5},{%6,%7},{%0,%1};"
        : "+r"(c[0]), "+r"(c[1])
        : "r"(a[0]), "r"(a[1]), "r"(a[2]), "r"(a[3]), "r"(b[0]), "r"(b[1]));
}

#define LDSM_X4(r0, r1, r2, r3, addr) \
    asm volatile("ldmatrix.sync.aligned.m8n8.x4.shared.b16 {%0,%1,%2,%3}, [%4];" \
                 : "=r"(r0), "=r"(r1), "=r"(r2), "=r"(r3) : "r"(addr))

// Packed tile layout: rows x 32 fp16 (64B/row), two rows per 128B line,
// XOR swizzle -> conflict-free for cp.async fill and ldmatrix.
__device__ __forceinline__ uint32_t sw_off(int r, int kb) {
    uint32_t L = ((uint32_t)(r >> 1) << 7) | ((uint32_t)(r & 1) << 6) | (uint32_t)kb;
    return L ^ ((L >> 3) & 0x70);
}

#define KTILES 12          // 384 / 32
#define CPA(dst, src) \
    asm volatile("cp.async.cg.shared.global [%0], [%1], 16;" :: "r"(dst), "l"(src))

// ---------------------------------------------------------------------------
// 0) prologue: normalize features (blocks < 768, 2 rows per warp -> MLP=2)
//    + centroid scale / zero. sqrt(w_m) folded into features AND centroids.
// ---------------------------------------------------------------------------
__global__ void prep_kernel(const float* __restrict__ st_i,
                            const float* __restrict__ st_j,
                            const float* __restrict__ car_i,
                            const float* __restrict__ car_j,
                            const float* __restrict__ pl_i,
                            const float* __restrict__ pl_j,
                            const float* __restrict__ cst,
                            const float* __restrict__ ccar,
                            const float* __restrict__ cpl,
                            const float* __restrict__ conc,
                            float* __restrict__ out, int out_size) {
    int b = blockIdx.x;
    if (b < 768) {
        int wq = b * 8 + (threadIdx.x >> 5);   // warp handles rows 2wq, 2wq+1
        int lane = threadIdx.x & 31;
        int g0 = wq * 2;
        int t = g0 / BHALF;                    // both rows in same tensor (2048 even)
        int r0 = g0 % BHALF;
        const float* src;
        switch (t) {
            case 0: src = st_i;  break;
            case 1: src = st_j;  break;
            case 2: src = car_i; break;
            case 3: src = car_j; break;
            case 4: src = pl_i;  break;
            default: src = pl_j; break;
        }
        int m    = t >> 1;
        int half = t & 1;
        float sw = (m == 0) ? 0.6324555320336759f : 0.5477225575051661f;  // sqrt(w)

        float4 va = *reinterpret_cast<const float4*>(&src[(size_t)r0 * DMOD + lane * 4]);
        float4 vb = *reinterpret_cast<const float4*>(&src[(size_t)(r0 + 1) * DMOD + lane * 4]);
        float sa = va.x * va.x + va.y * va.y + va.z * va.z + va.w * va.w;
        float sb = vb.x * vb.x + vb.y * vb.y + vb.z * vb.z + vb.w * vb.w;
        #pragma unroll
        for (int o = 16; o; o >>= 1) {
            sa += __shfl_xor_sync(0xffffffffu, sa, o);
            sb += __shfl_xor_sync(0xffffffffu, sb, o);
        }
        float wsa = sw / fmaxf(sqrtf(sa), 1e-12f);
        float wsb = sw / fmaxf(sqrtf(sb), 1e-12f);

        size_t basea = (size_t)(half * BHALF + r0) * DK + m * DMOD + lane * 4;
        *reinterpret_cast<__half2*>(&g_F[basea])          = __floats2half2_rn(va.x * wsa, va.y * wsa);
        *reinterpret_cast<__half2*>(&g_F[basea + 2])      = __floats2half2_rn(va.z * wsa, va.w * wsa);
        *reinterpret_cast<__half2*>(&g_F[basea + DK])     = __floats2half2_rn(vb.x * wsb, vb.y * wsb);
        *reinterpret_cast<__half2*>(&g_F[basea + DK + 2]) = __floats2half2_rn(vb.z * wsb, vb.w * wsb);
    } else {
        int idx = (b - 768) * 256 + threadIdx.x;
        if (idx < NROW) { g_rowsum[idx] = 0.0f; g_sumexp[idx] = 0.0f; }
        if (idx < out_size) out[idx] = 0.0f;
        if (idx < NC * DK) {
            int c   = idx / DK;
            int rem = idx % DK;
            int m   = rem >> 7;
            int d   = rem & 127;
            const float* cen = (m == 0) ? cst : ((m == 1) ? ccar : cpl);
            float sw = (m == 0) ? 0.6324555320336759f : 0.5477225575051661f;
            g_Cp[idx] = __float2half_rn(cen[c * DMOD + d] * (sw / (conc[m * NC + c] + 1e-12f)));
        }
    }
}

// ---------------------------------------------------------------------------
// 1) fused GEMMs, ONE kernel, 3 CTAs/SM (the R8 retry with correct bounds):
//    CTAs [0,528): sims tiles (128x128, triangular, fp16 acc).
//    CTAs [528,784): proto tiles (64x128, f32 acc, fused softmax).
//    Proto CTAs pack into the sims grid's second-wave slack.
// ---------------------------------------------------------------------------
__global__ void __launch_bounds__(256, 3) gemms_f16(const int* __restrict__ labels) {
    __shared__ __align__(128) __half As[3][4096];   // 24 KB
    __shared__ __align__(128) __half Bs[3][4096];   // 24 KB

    const int cta  = blockIdx.x;
    const int tid  = threadIdx.x;
    const int lane = tid & 31;
    const int w    = tid >> 5;
    const int wm   = w >> 2;
    const int wn   = w & 3;
    const int g    = lane >> 2;
    const int t    = lane & 3;
    const int sub  = lane >> 3;
    const int lr   = lane & 7;

    uint32_t sA = smem_u32(As), sB = smem_u32(Bs);

    if (cta < SIMS_CTAS) {
        // ================= sims: S = g_F @ g_F^T, 128x128 tile =================
        int n = cta;
        int by = 0;
        while (n >= 32 - by) { n -= 32 - by; by++; }
        int bx = by + n;
        const bool diffblk = (bx != by);
        const int row0 = by * 128, col0 = bx * 128;

        uint32_t dst_off[2];
        int src_off[2];
        #pragma unroll
        for (int l = 0; l < 2; l++) {
            int v = tid + l * 256;
            int r = v >> 2, c8 = v & 3;
            dst_off[l] = sw_off(r, c8 * 16);
            src_off[l] = r * DK + c8 * 8;
        }
        uint32_t offA[2][4], offB[2][2];
        #pragma unroll
        for (int s = 0; s < 2; s++) {
            int kbA = s * 32 + (sub >> 1) * 16;
            #pragma unroll
            for (int i = 0; i < 4; i++)
                offA[s][i] = sw_off(wm * 64 + i * 16 + (sub & 1) * 8 + lr, kbA);
            int kbB = s * 32 + (sub & 1) * 16;
            #pragma unroll
            for (int jp = 0; jp < 2; jp++)
                offB[s][jp] = sw_off(wn * 32 + jp * 16 + (sub >> 1) * 8 + lr, kbB);
        }

        uint32_t acc[4][4][2];
        #pragma unroll
        for (int i = 0; i < 4; i++)
            #pragma unroll
            for (int j = 0; j < 4; j++) { acc[i][j][0] = 0u; acc[i][j][1] = 0u; }

        const __half* Abase = g_F + (size_t)row0 * DK;
        const __half* Bbase = g_F + (size_t)col0 * DK;

        #pragma unroll
        for (int pf = 0; pf < 2; pf++) {
            #pragma unroll
            for (int l = 0; l < 2; l++) {
                CPA(sA + pf * 8192 + dst_off[l], __cvta_generic_to_global(Abase + pf * 32 + src_off[l]));
                CPA(sB + pf * 8192 + dst_off[l], __cvta_generic_to_global(Bbase + pf * 32 + src_off[l]));
            }
            asm volatile("cp.async.commit_group;" ::: "memory");
        }
        #pragma unroll 1
        for (int it = 0; it < KTILES; it++) {
            if (it < KTILES - 1) asm volatile("cp.async.wait_group 1;" ::: "memory");
            else                 asm volatile("cp.async.wait_group 0;" ::: "memory");
            __syncthreads();
            if (it + 2 < KTILES) {
                int st = (it + 2) % 3;
                #pragma unroll
                for (int l = 0; l < 2; l++) {
                    CPA(sA + st * 8192 + dst_off[l], __cvta_generic_to_global(Abase + (it + 2) * 32 + src_off[l]));
                    CPA(sB + st * 8192 + dst_off[l], __cvta_generic_to_global(Bbase + (it + 2) * 32 + src_off[l]));
                }
                asm volatile("cp.async.commit_group;" ::: "memory");
            }
            uint32_t bA = sA + (it % 3) * 8192, bB = sB + (it % 3) * 8192;
            #pragma unroll
            for (int s = 0; s < 2; s++) {
                uint32_t a[4][4], b[4][2];
                #pragma unroll
                for (int i = 0; i < 4; i++)
                    LDSM_X4(a[i][0], a[i][1], a[i][2], a[i][3], bA + offA[s][i]);
                #pragma unroll
                for (int jp = 0; jp < 2; jp++)
                    LDSM_X4(b[2 * jp][0], b[2 * jp][1], b[2 * jp + 1][0], b[2 * jp + 1][1],
                            bB + offB[s][jp]);
                #pragma unroll
                for (int i = 0; i < 4; i++)
                    #pragma unroll
                    for (int j = 0; j < 4; j++)
                        mma16816h(acc[i][j], a[i], b[j]);
            }
        }
        __syncthreads();

        // ---- epilogue (rs/rc reuse stage-0 smem) ----
        float* rs = reinterpret_cast<float*>(As);
        float* rc = rs + 128;
        if (tid < 128) { rs[tid] = 0.0f; rc[tid] = 0.0f; }
        __syncthreads();

        const float S2 = 2.8853900817779268f;   // 2/ln2 (1/TEMP = 2)
        float colsum[4][2];
        #pragma unroll
        for (int j = 0; j < 4; j++) { colsum[j][0] = 0.0f; colsum[j][1] = 0.0f; }

        #pragma unroll
        for (int i = 0; i < 4; i++) {
            #pragma unroll
            for (int h = 0; h < 2; h++) {
                int rl = wm * 64 + i * 16 + h * 8 + g;
                int gi = row0 + rl;
                int pj = (gi + BHALF) & (NROW - 1);
                float sum = 0.0f;
                #pragma unroll
                for (int j = 0; j < 4; j++) {
                    float2 sv = __half22float2(*reinterpret_cast<__half2*>(&acc[i][j][h]));
                    float e0 = fexp2(sv.x * S2);
                    float e1 = fexp2(sv.y * S2);
                    sum += e0 + e1;
                    colsum[j][0] += e0;
                    colsum[j][1] += e1;
                    int gj = col0 + wn * 32 + j * 8 + 2 * t;
                    if (gj == pj)     { g_pos[gi] = e0; if (diffblk) g_pos[gj]     = e0; }
                    if (gj + 1 == pj) { g_pos[gi] = e1; if (diffblk) g_pos[gj + 1] = e1; }
                }
                sum += __shfl_xor_sync(0xffffffffu, sum, 1);
                sum += __shfl_xor_sync(0xffffffffu, sum, 2);
                if (t == 0) atomicAdd(&rs[rl], sum);
            }
        }
        if (diffblk) {
            #pragma unroll
            for (int j = 0; j < 4; j++) {
                #pragma unroll
                for (int p = 0; p < 2; p++) {
                    float v = colsum[j][p];
                    v += __shfl_xor_sync(0xffffffffu, v, 4);
                    v += __shfl_xor_sync(0xffffffffu, v, 8);
                    v += __shfl_xor_sync(0xffffffffu, v, 16);
                    if (g == 0) atomicAdd(&rc[wn * 32 + j * 8 + 2 * t + p], v);
                }
            }
        }
        __syncthreads();
        if (tid < 128) {
            atomicAdd(&g_rowsum[row0 + tid], rs[tid]);
            if (diffblk) atomicAdd(&g_rowsum[col0 + tid], rc[tid]);
        }
    } else {
        // ===== proto: logits = g_F @ g_Cp^T, 64x128 tile, fused softmax =====
        int p = cta - SIMS_CTAS;
        const int row0 = (p >> 2) * 64;
        const int col0 = (p & 3) * 128;

        uint32_t dstA;
        int srcA;
        {
            int r = tid >> 2, c8 = tid & 3;
            dstA = sw_off(r, c8 * 16);
            srcA = r * DK + c8 * 8;
        }
        uint32_t dstB[2];
        int srcB[2];
        #pragma unroll
        for (int l = 0; l < 2; l++) {
            int v = tid + l * 256;
            int r = v >> 2, c8 = v & 3;
            dstB[l] = sw_off(r, c8 * 16);
            srcB[l] = r * DK + c8 * 8;
        }
        uint32_t offA[2][2], offB[2][2];
        #pragma unroll
        for (int s = 0; s < 2; s++) {
            int kbA = s * 32 + (sub >> 1) * 16;
            #pragma unroll
            for (int i = 0; i < 2; i++)
                offA[s][i] = sw_off(wm * 32 + i * 16 + (sub & 1) * 8 + lr, kbA);
            int kbB = s * 32 + (sub & 1) * 16;
            #pragma unroll
            for (int jp = 0; jp < 2; jp++)
                offB[s][jp] = sw_off(wn * 32 + jp * 16 + (sub >> 1) * 8 + lr, kbB);
        }

        float acc[2][4][4];
        #pragma unroll
        for (int i = 0; i < 2; i++)
            #pragma unroll
            for (int j = 0; j < 4; j++)
                #pragma unroll
                for (int r = 0; r < 4; r++) acc[i][j][r] = 0.0f;

        const __half* Abase = g_F + (size_t)row0 * DK;
        const __half* Bbase = g_Cp + (size_t)col0 * DK;

        #pragma unroll
        for (int pf = 0; pf < 2; pf++) {
            CPA(sA + pf * 8192 + dstA, __cvta_generic_to_global(Abase + pf * 32 + srcA));
            #pragma unroll
            for (int l = 0; l < 2; l++)
                CPA(sB + pf * 8192 + dstB[l], __cvta_generic_to_global(Bbase + pf * 32 + srcB[l]));
            asm volatile("cp.async.commit_group;" ::: "memory");
        }
        #pragma unroll 1
        for (int it = 0; it < KTILES; it++) {
            if (it < KTILES - 1) asm volatile("cp.async.wait_group 1;" ::: "memory");
            else                 asm volatile("cp.async.wait_group 0;" ::: "memory");
            __syncthreads();
            if (it + 2 < KTILES) {
                int st = (it + 2) % 3;
                CPA(sA + st * 8192 + dstA, __cvta_generic_to_global(Abase + (it + 2) * 32 + srcA));
                #pragma unroll
                for (int l = 0; l < 2; l++)
                    CPA(sB + st * 8192 + dstB[l], __cvta_generic_to_global(Bbase + (it + 2) * 32 + srcB[l]));
                asm volatile("cp.async.commit_group;" ::: "memory");
            }
            uint32_t bA = sA + (it % 3) * 8192, bB = sB + (it % 3) * 8192;
            #pragma unroll
            for (int s = 0; s < 2; s++) {
                uint32_t a[2][4], b[4][2];
                #pragma unroll
                for (int i = 0; i < 2; i++)
                    LDSM_X4(a[i][0], a[i][1], a[i][2], a[i][3], bA + offA[s][i]);
                #pragma unroll
                for (int jp = 0; jp < 2; jp++)
                    LDSM_X4(b[2 * jp][0], b[2 * jp][1], b[2 * jp + 1][0], b[2 * jp + 1][1],
                            bB + offB[s][jp]);
                #pragma unroll
                for (int i = 0; i < 2; i++)
                    #pragma unroll
                    for (int j = 0; j < 4; j++)
                        mma16816f(acc[i][j], a[i], b[j]);
            }
        }

        // ---- fused softmax epilogue ----
        const float LOG2E = 1.4426950408889634f;
        #pragma unroll
        for (int i = 0; i < 2; i++) {
            #pragma unroll
            for (int h = 0; h < 2; h++) {
                int gi  = row0 + wm * 32 + i * 16 + h * 8 + g;
                int lab = labels[gi];
                float sum = 0.0f;
                #pragma unroll
                for (int j = 0; j < 4; j++) {
                    float l0 = acc[i][j][2 * h];
                    float l1 = acc[i][j][2 * h + 1];
                    sum += fexp2(l0 * LOG2E) + fexp2(l1 * LOG2E);
                    int gj = col0 + wn * 32 + j * 8 + 2 * t;
                    if (gj == lab)     g_labval[gi] = l0;
                    if (gj + 1 == lab) g_labval[gi] = l1;
                }
                sum += __shfl_xor_sync(0xffffffffu, sum, 1);
                sum += __shfl_xor_sync(0xffffffffu, sum, 2);
                if (t == 0) atomicAdd(&g_sumexp[gi], sum);
            }
        }
    }
}

// ---------------------------------------------------------------------------
// 2) Finalize: trivial per-row combine -> mean (4096 threads)
// ---------------------------------------------------------------------------
__global__ void finalize_kernel(float* __restrict__ out) {
    int row  = blockIdx.x * blockDim.x + threadIdx.x;
    int lane = threadIdx.x & 31;
    float loss = 0.0f;
    if (row < NROW) {
        float loss2 = __logf(g_sumexp[row]) - g_labval[row];
        float loss1 = __logf((g_rowsum[row] - 7.3890560989306495f) / g_pos[row]); // diag=e^2
        loss = (loss1 + loss2) * (1.0f / NROW);
    }
    #pragma unroll
    for (int o = 16; o; o >>= 1) loss += __shfl_xor_sync(0xffffffffu, loss, o);
    if (lane == 0) atomicAdd(out, loss);
}

// ---------------------------------------------------------------------------
extern "C" void kernel_launch(void* const* d_in, const int* in_sizes, int n_in,
                              void* d_out, int out_size) {
    const float* st_i  = (const float*)d_in[0];
    const float* st_j  = (const float*)d_in[1];
    const float* car_i = (const float*)d_in[2];
    const float* car_j = (const float*)d_in[3];
    const float* pl_i  = (const float*)d_in[4];
    const float* pl_j  = (const float*)d_in[5];
    const int*   lab   = (const int*)d_in[6];
    const float* cst   = (const float*)d_in[7];
    const float* ccar  = (const float*)d_in[8];
    const float* cpl   = (const float*)d_in[9];
    const float* conc  = (const float*)d_in[10];
    float* out = (float*)d_out;

    prep_kernel<<<768 + 768, 256>>>(st_i, st_j, car_i, car_j, pl_i, pl_j,
                                    cst, ccar, cpl, conc, out, out_size);

    gemms_f16<<<SIMS_CTAS + PROTO_CTAS, 256>>>(lab);   // sims ∥ proto in one grid

    finalize_kernel<<<NROW / 256, 256>>>(out);
}

// round 14
// speedup vs baseline: 1.2892x; 1.0577x over previous
#include <cuda_runtime.h>
#include <cuda_fp16.h>
#include <math.h>
#include <stdint.h>

// Problem constants
#define NROW 4096
#define BHALF 2048
#define DK   384
#define DMOD 128
#define NC   512

#define SIMS_CTAS 528
#define PROTO_CTAS 256

// Scratch (device globals)
// Single feature array scaled by sqrt(w_m): sims = g_F@g_F^T, proto = g_F@g_Cp^T
__device__ __half g_F[NROW * DK];
__device__ __half g_Cp[NC * DK];     // centroids * sqrt(w_m)/(conc+1e-12)
__device__ float g_rowsum[NROW];
__device__ float g_pos[NROW];
__device__ float g_sumexp[NROW];     // proto row sum of exp(logit)
__device__ float g_labval[NROW];     // proto logit at the label column

// ---------------------------------------------------------------------------
// helpers
// ---------------------------------------------------------------------------
__device__ __forceinline__ uint32_t smem_u32(const void* p) {
    uint32_t a;
    asm("{ .reg .u64 t; cvta.to.shared.u64 t, %1; cvt.u32.u64 %0, t; }" : "=r"(a) : "l"(p));
    return a;
}

// fast exp2 on FMA pipe
__device__ __forceinline__ float fexp2(float t) {
    float r = t + 12582912.0f;
    int   i = __float_as_int(r) - 0x4B400000;
    float f = t - (r - 12582912.0f);
    float p = 1.3333558e-3f;
    p = fmaf(p, f, 9.6181291e-3f);
    p = fmaf(p, f, 5.5504109e-2f);
    p = fmaf(p, f, 2.4022651e-1f);
    p = fmaf(p, f, 6.9314718e-1f);
    p = fmaf(p, f, 1.0f);
    return __int_as_float(__float_as_int(p) + (i << 23));
}

// f32-accumulate fp16 MMA (proto)
__device__ __forceinline__ void mma16816f(float* c, const uint32_t* a, const uint32_t* b) {
    asm volatile(
        "mma.sync.aligned.m16n8k16.row.col.f32.f16.f16.f32 "
        "{%0,%1,%2,%3},{%4,%5,%6,%7},{%8,%9},{%0,%1,%2,%3};"
        : "+f"(c[0]), "+f"(c[1]), "+f"(c[2]), "+f"(c[3])
        : "r"(a[0]), "r"(a[1]), "r"(a[2]), "r"(a[3]), "r"(b[0]), "r"(b[1]));
}
// f16-accumulate fp16 MMA (sims)
__device__ __forceinline__ void mma16816h(uint32_t* c, const uint32_t* a, const uint32_t* b) {
    asm volatile(
        "mma.sync.aligned.m16n8k16.row.col.f16.f16.f16.f16 "
        "{%0,%1},{%2,%3,%4,%5},{%6,%7},{%0,%1};"
        : "+r"(c[0]), "+r"(c[1])
        : "r"(a[0]), "r"(a[1]), "r"(a[2]), "r"(a[3]), "r"(b[0]), "r"(b[1]));
}

#define LDSM_X4(r0, r1, r2, r3, addr) \
    asm volatile("ldmatrix.sync.aligned.m8n8.x4.shared.b16 {%0,%1,%2,%3}, [%4];" \
                 : "=r"(r0), "=r"(r1), "=r"(r2), "=r"(r3) : "r"(addr))

// Packed tile layout: rows x 32 fp16 (64B/row), two rows per 128B line,
// XOR swizzle -> conflict-free for cp.async fill and ldmatrix.
__device__ __forceinline__ uint32_t sw_off(int r, int kb) {
    uint32_t L = ((uint32_t)(r >> 1) << 7) | ((uint32_t)(r & 1) << 6) | (uint32_t)kb;
    return L ^ ((L >> 3) & 0x70);
}

#define KTILES 12          // 384 / 32
#define CPA(dst, src) \
    asm volatile("cp.async.cg.shared.global [%0], [%1], 16;" :: "r"(dst), "l"(src))

// ---------------------------------------------------------------------------
// 0) prologue:
//    blocks [0,384): normalize, one warp per 4 rows (MLP=4)
//    blocks [384,576): centroid scale (4 elems/thread, vectorized) + zeroing
// ---------------------------------------------------------------------------
__global__ void prep_kernel(const float* __restrict__ st_i,
                            const float* __restrict__ st_j,
                            const float* __restrict__ car_i,
                            const float* __restrict__ car_j,
                            const float* __restrict__ pl_i,
                            const float* __restrict__ pl_j,
                            const float* __restrict__ cst,
                            const float* __restrict__ ccar,
                            const float* __restrict__ cpl,
                            const float* __restrict__ conc,
                            float* __restrict__ out, int out_size) {
    int b = blockIdx.x;
    if (b < 384) {
        int wq = b * 8 + (threadIdx.x >> 5);   // warp handles rows 4wq..4wq+3
        int lane = threadIdx.x & 31;
        int g0 = wq * 4;
        int t = g0 / BHALF;                    // all 4 rows in same tensor (2048%4==0)
        int r0 = g0 % BHALF;
        const float* src;
        switch (t) {
            case 0: src = st_i;  break;
            case 1: src = st_j;  break;
            case 2: src = car_i; break;
            case 3: src = car_j; break;
            case 4: src = pl_i;  break;
            default: src = pl_j; break;
        }
        int m    = t >> 1;
        int half = t & 1;
        float sw = (m == 0) ? 0.6324555320336759f : 0.5477225575051661f;  // sqrt(w)

        float4 v[4];
        float ss[4];
        #pragma unroll
        for (int q = 0; q < 4; q++) {
            v[q] = *reinterpret_cast<const float4*>(&src[(size_t)(r0 + q) * DMOD + lane * 4]);
            ss[q] = v[q].x * v[q].x + v[q].y * v[q].y + v[q].z * v[q].z + v[q].w * v[q].w;
        }
        #pragma unroll
        for (int o = 16; o; o >>= 1) {
            #pragma unroll
            for (int q = 0; q < 4; q++)
                ss[q] += __shfl_xor_sync(0xffffffffu, ss[q], o);
        }
        size_t base0 = (size_t)(half * BHALF + r0) * DK + m * DMOD + lane * 4;
        #pragma unroll
        for (int q = 0; q < 4; q++) {
            float ws = sw / fmaxf(sqrtf(ss[q]), 1e-12f);
            size_t base = base0 + (size_t)q * DK;
            *reinterpret_cast<__half2*>(&g_F[base])     = __floats2half2_rn(v[q].x * ws, v[q].y * ws);
            *reinterpret_cast<__half2*>(&g_F[base + 2]) = __floats2half2_rn(v[q].z * ws, v[q].w * ws);
        }
    } else {
        int tidg = (b - 384) * 256 + threadIdx.x;   // 0..49151
        if (tidg < NROW) { g_rowsum[tidg] = 0.0f; g_sumexp[tidg] = 0.0f; }
        if (tidg < out_size) out[tidg] = 0.0f;
        int idx4 = tidg * 4;                        // 4 consecutive elements of g_Cp
        if (idx4 < NC * DK) {
            int c   = idx4 / DK;
            int rem = idx4 % DK;                    // multiple of 4; same modality block
            int m   = rem >> 7;
            int d   = rem & 127;
            const float* cen = (m == 0) ? cst : ((m == 1) ? ccar : cpl);
            float sw = (m == 0) ? 0.6324555320336759f : 0.5477225575051661f;
            float scale = sw / (conc[m * NC + c] + 1e-12f);
            float4 cv = *reinterpret_cast<const float4*>(&cen[c * DMOD + d]);
            *reinterpret_cast<__half2*>(&g_Cp[idx4])     = __floats2half2_rn(cv.x * scale, cv.y * scale);
            *reinterpret_cast<__half2*>(&g_Cp[idx4 + 2]) = __floats2half2_rn(cv.z * scale, cv.w * scale);
        }
    }
}

// ---------------------------------------------------------------------------
// 1) fused GEMMs, ONE kernel, 3 CTAs/SM:
//    CTAs [0,528): sims tiles (128x128, triangular, fp16 acc).
//    CTAs [528,784): proto tiles (64x128, f32 acc, fused softmax).
// ---------------------------------------------------------------------------
__global__ void __launch_bounds__(256, 3) gemms_f16(const int* __restrict__ labels) {
    __shared__ __align__(128) __half As[3][4096];   // 24 KB
    __shared__ __align__(128) __half Bs[3][4096];   // 24 KB

    const int cta  = blockIdx.x;
    const int tid  = threadIdx.x;
    const int lane = tid & 31;
    const int w    = tid >> 5;
    const int wm   = w >> 2;
    const int wn   = w & 3;
    const int g    = lane >> 2;
    const int t    = lane & 3;
    const int sub  = lane >> 3;
    const int lr   = lane & 7;

    uint32_t sA = smem_u32(As), sB = smem_u32(Bs);

    if (cta < SIMS_CTAS) {
        // ================= sims: S = g_F @ g_F^T, 128x128 tile =================
        int n = cta;
        int by = 0;
        while (n >= 32 - by) { n -= 32 - by; by++; }
        int bx = by + n;
        const bool diffblk = (bx != by);
        const int row0 = by * 128, col0 = bx * 128;

        uint32_t dst_off[2];
        int src_off[2];
        #pragma unroll
        for (int l = 0; l < 2; l++) {
            int v = tid + l * 256;
            int r = v >> 2, c8 = v & 3;
            dst_off[l] = sw_off(r, c8 * 16);
            src_off[l] = r * DK + c8 * 8;
        }
        uint32_t offA[2][4], offB[2][2];
        #pragma unroll
        for (int s = 0; s < 2; s++) {
            int kbA = s * 32 + (sub >> 1) * 16;
            #pragma unroll
            for (int i = 0; i < 4; i++)
                offA[s][i] = sw_off(wm * 64 + i * 16 + (sub & 1) * 8 + lr, kbA);
            int kbB = s * 32 + (sub & 1) * 16;
            #pragma unroll
            for (int jp = 0; jp < 2; jp++)
                offB[s][jp] = sw_off(wn * 32 + jp * 16 + (sub >> 1) * 8 + lr, kbB);
        }

        uint32_t acc[4][4][2];
        #pragma unroll
        for (int i = 0; i < 4; i++)
            #pragma unroll
            for (int j = 0; j < 4; j++) { acc[i][j][0] = 0u; acc[i][j][1] = 0u; }

        const __half* Abase = g_F + (size_t)row0 * DK;
        const __half* Bbase = g_F + (size_t)col0 * DK;

        #pragma unroll
        for (int pf = 0; pf < 2; pf++) {
            #pragma unroll
            for (int l = 0; l < 2; l++) {
                CPA(sA + pf * 8192 + dst_off[l], __cvta_generic_to_global(Abase + pf * 32 + src_off[l]));
                CPA(sB + pf * 8192 + dst_off[l], __cvta_generic_to_global(Bbase + pf * 32 + src_off[l]));
            }
            asm volatile("cp.async.commit_group;" ::: "memory");
        }
        #pragma unroll 1
        for (int it = 0; it < KTILES; it++) {
            if (it < KTILES - 1) asm volatile("cp.async.wait_group 1;" ::: "memory");
            else                 asm volatile("cp.async.wait_group 0;" ::: "memory");
            __syncthreads();
            if (it + 2 < KTILES) {
                int st = (it + 2) % 3;
                #pragma unroll
                for (int l = 0; l < 2; l++) {
                    CPA(sA + st * 8192 + dst_off[l], __cvta_generic_to_global(Abase + (it + 2) * 32 + src_off[l]));
                    CPA(sB + st * 8192 + dst_off[l], __cvta_generic_to_global(Bbase + (it + 2) * 32 + src_off[l]));
                }
                asm volatile("cp.async.commit_group;" ::: "memory");
            }
            uint32_t bA = sA + (it % 3) * 8192, bB = sB + (it % 3) * 8192;
            #pragma unroll
            for (int s = 0; s < 2; s++) {
                uint32_t a[4][4], b[4][2];
                #pragma unroll
                for (int i = 0; i < 4; i++)
                    LDSM_X4(a[i][0], a[i][1], a[i][2], a[i][3], bA + offA[s][i]);
                #pragma unroll
                for (int jp = 0; jp < 2; jp++)
                    LDSM_X4(b[2 * jp][0], b[2 * jp][1], b[2 * jp + 1][0], b[2 * jp + 1][1],
                            bB + offB[s][jp]);
                #pragma unroll
                for (int i = 0; i < 4; i++)
                    #pragma unroll
                    for (int j = 0; j < 4; j++)
                        mma16816h(acc[i][j], a[i], b[j]);
            }
        }
        __syncthreads();

        // ---- epilogue (rs/rc reuse stage-0 smem) ----
        float* rs = reinterpret_cast<float*>(As);
        float* rc = rs + 128;
        if (tid < 128) { rs[tid] = 0.0f; rc[tid] = 0.0f; }
        __syncthreads();

        const float S2 = 2.8853900817779268f;   // 2/ln2 (1/TEMP = 2)
        float colsum[4][2];
        #pragma unroll
        for (int j = 0; j < 4; j++) { colsum[j][0] = 0.0f; colsum[j][1] = 0.0f; }

        #pragma unroll
        for (int i = 0; i < 4; i++) {
            #pragma unroll
            for (int h = 0; h < 2; h++) {
                int rl = wm * 64 + i * 16 + h * 8 + g;
                int gi = row0 + rl;
                int pj = (gi + BHALF) & (NROW - 1);
                float sum = 0.0f;
                #pragma unroll
                for (int j = 0; j < 4; j++) {
                    float2 sv = __half22float2(*reinterpret_cast<__half2*>(&acc[i][j][h]));
                    float e0 = fexp2(sv.x * S2);
                    float e1 = fexp2(sv.y * S2);
                    sum += e0 + e1;
                    colsum[j][0] += e0;
                    colsum[j][1] += e1;
                    int gj = col0 + wn * 32 + j * 8 + 2 * t;
                    if (gj == pj)     { g_pos[gi] = e0; if (diffblk) g_pos[gj]     = e0; }
                    if (gj + 1 == pj) { g_pos[gi] = e1; if (diffblk) g_pos[gj + 1] = e1; }
                }
                sum += __shfl_xor_sync(0xffffffffu, sum, 1);
                sum += __shfl_xor_sync(0xffffffffu, sum, 2);
                if (t == 0) atomicAdd(&rs[rl], sum);
            }
        }
        if (diffblk) {
            #pragma unroll
            for (int j = 0; j < 4; j++) {
                #pragma unroll
                for (int p = 0; p < 2; p++) {
                    float v = colsum[j][p];
                    v += __shfl_xor_sync(0xffffffffu, v, 4);
                    v += __shfl_xor_sync(0xffffffffu, v, 8);
                    v += __shfl_xor_sync(0xffffffffu, v, 16);
                    if (g == 0) atomicAdd(&rc[wn * 32 + j * 8 + 2 * t + p], v);
                }
            }
        }
        __syncthreads();
        if (tid < 128) {
            atomicAdd(&g_rowsum[row0 + tid], rs[tid]);
            if (diffblk) atomicAdd(&g_rowsum[col0 + tid], rc[tid]);
        }
    } else {
        // ===== proto: logits = g_F @ g_Cp^T, 64x128 tile, fused softmax =====
        int p = cta - SIMS_CTAS;
        const int row0 = (p >> 2) * 64;
        const int col0 = (p & 3) * 128;

        uint32_t dstA;
        int srcA;
        {
            int r = tid >> 2, c8 = tid & 3;
            dstA = sw_off(r, c8 * 16);
            srcA = r * DK + c8 * 8;
        }
        uint32_t dstB[2];
        int srcB[2];
        #pragma unroll
        for (int l = 0; l < 2; l++) {
            int v = tid + l * 256;
            int r = v >> 2, c8 = v & 3;
            dstB[l] = sw_off(r, c8 * 16);
            srcB[l] = r * DK + c8 * 8;
        }
        uint32_t offA[2][2], offB[2][2];
        #pragma unroll
        for (int s = 0; s < 2; s++) {
            int kbA = s * 32 + (sub >> 1) * 16;
            #pragma unroll
            for (int i = 0; i < 2; i++)
                offA[s][i] = sw_off(wm * 32 + i * 16 + (sub & 1) * 8 + lr, kbA);
            int kbB = s * 32 + (sub & 1) * 16;
            #pragma unroll
            for (int jp = 0; jp < 2; jp++)
                offB[s][jp] = sw_off(wn * 32 + jp * 16 + (sub >> 1) * 8 + lr, kbB);
        }

        float acc[2][4][4];
        #pragma unroll
        for (int i = 0; i < 2; i++)
            #pragma unroll
            for (int j = 0; j < 4; j++)
                #pragma unroll
                for (int r = 0; r < 4; r++) acc[i][j][r] = 0.0f;

        const __half* Abase = g_F + (size_t)row0 * DK;
        const __half* Bbase = g_Cp + (size_t)col0 * DK;

        #pragma unroll
        for (int pf = 0; pf < 2; pf++) {
            CPA(sA + pf * 8192 + dstA, __cvta_generic_to_global(Abase + pf * 32 + srcA));
            #pragma unroll
            for (int l = 0; l < 2; l++)
                CPA(sB + pf * 8192 + dstB[l], __cvta_generic_to_global(Bbase + pf * 32 + srcB[l]));
            asm volatile("cp.async.commit_group;" ::: "memory");
        }
        #pragma unroll 1
        for (int it = 0; it < KTILES; it++) {
            if (it < KTILES - 1) asm volatile("cp.async.wait_group 1;" ::: "memory");
            else                 asm volatile("cp.async.wait_group 0;" ::: "memory");
            __syncthreads();
            if (it + 2 < KTILES) {
                int st = (it + 2) % 3;
                CPA(sA + st * 8192 + dstA, __cvta_generic_to_global(Abase + (it + 2) * 32 + srcA));
                #pragma unroll
                for (int l = 0; l < 2; l++)
                    CPA(sB + st * 8192 + dstB[l], __cvta_generic_to_global(Bbase + (it + 2) * 32 + srcB[l]));
                asm volatile("cp.async.commit_group;" ::: "memory");
            }
            uint32_t bA = sA + (it % 3) * 8192, bB = sB + (it % 3) * 8192;
            #pragma unroll
            for (int s = 0; s < 2; s++) {
                uint32_t a[2][4], b[4][2];
                #pragma unroll
                for (int i = 0; i < 2; i++)
                    LDSM_X4(a[i][0], a[i][1], a[i][2], a[i][3], bA + offA[s][i]);
                #pragma unroll
                for (int jp = 0; jp < 2; jp++)
                    LDSM_X4(b[2 * jp][0], b[2 * jp][1], b[2 * jp + 1][0], b[2 * jp + 1][1],
                            bB + offB[s][jp]);
                #pragma unroll
                for (int i = 0; i < 2; i++)
                    #pragma unroll
                    for (int j = 0; j < 4; j++)
                        mma16816f(acc[i][j], a[i], b[j]);
            }
        }

        // ---- fused softmax epilogue ----
        const float LOG2E = 1.4426950408889634f;
        #pragma unroll
        for (int i = 0; i < 2; i++) {
            #pragma unroll
            for (int h = 0; h < 2; h++) {
                int gi  = row0 + wm * 32 + i * 16 + h * 8 + g;
                int lab = labels[gi];
                float sum = 0.0f;
                #pragma unroll
                for (int j = 0; j < 4; j++) {
                    float l0 = acc[i][j][2 * h];
                    float l1 = acc[i][j][2 * h + 1];
                    sum += fexp2(l0 * LOG2E) + fexp2(l1 * LOG2E);
                    int gj = col0 + wn * 32 + j * 8 + 2 * t;
                    if (gj == lab)     g_labval[gi] = l0;
                    if (gj + 1 == lab) g_labval[gi] = l1;
                }
                sum += __shfl_xor_sync(0xffffffffu, sum, 1);
                sum += __shfl_xor_sync(0xffffffffu, sum, 2);
                if (t == 0) atomicAdd(&g_sumexp[gi], sum);
            }
        }
    }
}

// ---------------------------------------------------------------------------
// 2) Finalize: trivial per-row combine -> mean (4096 threads)
// ---------------------------------------------------------------------------
__global__ void finalize_kernel(float* __restrict__ out) {
    int row  = blockIdx.x * blockDim.x + threadIdx.x;
    int lane = threadIdx.x & 31;
    float loss = 0.0f;
    if (row < NROW) {
        float loss2 = __logf(g_sumexp[row]) - g_labval[row];
        float loss1 = __logf((g_rowsum[row] - 7.3890560989306495f) / g_pos[row]); // diag=e^2
        loss = (loss1 + loss2) * (1.0f / NROW);
    }
    #pragma unroll
    for (int o = 16; o; o >>= 1) loss += __shfl_xor_sync(0xffffffffu, loss, o);
    if (lane == 0) atomicAdd(out, loss);
}

// ---------------------------------------------------------------------------
extern "C" void kernel_launch(void* const* d_in, const int* in_sizes, int n_in,
                              void* d_out, int out_size) {
    const float* st_i  = (const float*)d_in[0];
    const float* st_j  = (const float*)d_in[1];
    const float* car_i = (const float*)d_in[2];
    const float* car_j = (const float*)d_in[3];
    const float* pl_i  = (const float*)d_in[4];
    const float* pl_j  = (const float*)d_in[5];
    const int*   lab   = (const int*)d_in[6];
    const float* cst   = (const float*)d_in[7];
    const float* ccar  = (const float*)d_in[8];
    const float* cpl   = (const float*)d_in[9];
    const float* conc  = (const float*)d_in[10];
    float* out = (float*)d_out;

    prep_kernel<<<384 + 192, 256>>>(st_i, st_j, car_i, car_j, pl_i, pl_j,
                                    cst, ccar, cpl, conc, out, out_size);

    gemms_f16<<<SIMS_CTAS + PROTO_CTAS, 256>>>(lab);   // sims ∥ proto in one grid

    finalize_kernel<<<NROW / 256, 256>>>(out);
}